// round 10
// baseline (speedup 1.0000x reference)
#include <cuda_runtime.h>
#include <cstdint>

#define THREADS  256
#define ITEMS    16
#define TILE     (THREADS * ITEMS)    // 4096
#define HALO     1024
#define HITEMS   (HALO / THREADS)     // 4
#define NWARPS   (THREADS / 32)       // 8
#define FULLMASK 0xFFFFFFFFu
#define DISC     0.99f

// packed terminal bits: bit (e & 127) lives in word ((e>>2)&... ) -- see pack_k.
// Layout per 128 elements: uint4 W; element e=4k+j (k=0..31, j=0..3) -> bit k of W[j].
#define MAXN_BITS_U4 262144            // covers n up to 33.5M elements (4 MB)
__device__ uint4 g_bits[MAXN_BITS_U4];

__global__ void __launch_bounds__(256)
pack_k(const int* __restrict__ term, int n)
{
    const int lane = threadIdx.x & 31;
    const int gw   = (blockIdx.x * 256 + threadIdx.x) >> 5;   // global warp id
    const int base = gw * 512;                                // 512 elements per warp
    if (base >= n) return;

    unsigned myx = 0, myy = 0, myz = 0, myw = 0;
    #pragma unroll
    for (int k = 0; k < 4; ++k) {
        int e = base + k * 128 + lane * 4;
        int4 tv = make_int4(0, 0, 0, 0);
        if (e + 3 < n)      tv = __ldcs((const int4*)(term + e));
        else {
            if (e + 0 < n) tv.x = term[e + 0];
            if (e + 1 < n) tv.y = term[e + 1];
            if (e + 2 < n) tv.z = term[e + 2];
            if (e + 3 < n) tv.w = term[e + 3];
        }
        unsigned w0 = __ballot_sync(FULLMASK, tv.x != 0);
        unsigned w1 = __ballot_sync(FULLMASK, tv.y != 0);
        unsigned w2 = __ballot_sync(FULLMASK, tv.z != 0);
        unsigned w3 = __ballot_sync(FULLMASK, tv.w != 0);
        if (lane == k) { myx = w0; myy = w1; myz = w2; myw = w3; }
    }
    if (lane < 4 && (unsigned)(gw * 4 + lane) < MAXN_BITS_U4)
        g_bits[gw * 4 + lane] = make_uint4(myx, myy, myz, myw);
}

// spread nibble bits to positions 0,4,8,12
__device__ __forceinline__ unsigned spread4(unsigned nib) {
    return (nib * 0x249u) & 0x1111u;
}

// y[t] = a[t]*y[t+1] + r[t],  a = terminal[t] ? 0 : DISC,  y[n] = 0 (FINAL_REWARD=0).
// Halo truncation: carry through 1024 non-terminal steps scales by 0.99^1024=3.4e-5;
// RMS tile contribution ~2e-6 relative (threshold 1e-3). Blocks fully independent.
__global__ void __launch_bounds__(THREADS, 6)
scan_k(const float* __restrict__ reward,
       const int*  __restrict__ term,      // direct reads only on ragged tails
       float*      __restrict__ out, int n)
{
    __shared__ float s_wA[NWARPS], s_wB[NWARPS];   // owned warp aggregates
    __shared__ float s_hA[NWARPS], s_hB[NWARPS];   // halo warp aggregates
    __shared__ float s_cA[NWARPS], s_cB[NWARPS];   // per-warp exclusive carries
    __shared__ float s_yin;

    // 0.99^k, k=0..16
    const float pw[17] = {
        1.0f, 0.99f, 0.9801f, 0.970299f, 0.96059601f,
        0.9509900499f, 0.941480149401f, 0.93206534790699f, 0.9227446944279201f,
        0.9135172474836409f, 0.9043820750088045f, 0.8953382542587165f,
        0.8863848717161293f, 0.8775210229989680f, 0.8687458127689783f,
        0.8600583546412885f, 0.8514577710948756f };

    const int t    = threadIdx.x;
    const int lane = t & 31;
    const int wid  = t >> 5;

    const int s  = (int)blockIdx.x * TILE;
    const int cs = s + t * ITEMS;                // owned chunk start
    const int hs = s + TILE + t * HITEMS;        // halo chunk start

    const bool ownFull = (s + TILE        <= n);
    const bool extFull = (s + TILE + HALO <= n);

    // ---------------- loads (front-batched for MLP) ----------------
    float    r[ITEMS];
    unsigned tmask = 0u, onemask = 0u;
    float    hr[HITEMS];
    unsigned htmask = 0u, honemask = 0u;

    if (ownFull) {
        const float4* rp = (const float4*)(reward + cs);
        float4 v0 = rp[0], v1 = rp[1], v2 = rp[2], v3 = rp[3];
        uint4  W  = g_bits[cs >> 7];               // broadcast: 8 threads share one
        r[0]=v0.x; r[1]=v0.y; r[2]=v0.z; r[3]=v0.w;
        r[4]=v1.x; r[5]=v1.y; r[6]=v1.z; r[7]=v1.w;
        r[8]=v2.x; r[9]=v2.y; r[10]=v2.z; r[11]=v2.w;
        r[12]=v3.x; r[13]=v3.y; r[14]=v3.z; r[15]=v3.w;
        const unsigned k0 = (unsigned)(cs >> 2) & 31u;   // multiple of 4
        tmask =  spread4((W.x >> k0) & 0xFu)
              | (spread4((W.y >> k0) & 0xFu) << 1)
              | (spread4((W.z >> k0) & 0xFu) << 2)
              | (spread4((W.w >> k0) & 0xFu) << 3);
    } else {
        #pragma unroll
        for (int i = 0; i < ITEMS; ++i) {
            int g = cs + i;
            if (g < n) {
                r[i] = reward[g];
                if (term[g] != 0) tmask |= (1u << i);
            } else { r[i] = 0.0f; onemask |= (1u << i); }
        }
    }

    if (extFull) {
        float4 hv = *(const float4*)(reward + hs);
        uint4  Wh = g_bits[hs >> 7];               // whole warp shares one -> broadcast
        hr[0]=hv.x; hr[1]=hv.y; hr[2]=hv.z; hr[3]=hv.w;
        const unsigned kh = (unsigned)(hs >> 2) & 31u;
        htmask = ((Wh.x >> kh) & 1u)
               | (((Wh.y >> kh) & 1u) << 1)
               | (((Wh.z >> kh) & 1u) << 2)
               | (((Wh.w >> kh) & 1u) << 3);
    } else {
        #pragma unroll
        for (int i = 0; i < HITEMS; ++i) {
            int g = hs + i;
            if (g < n) {
                hr[i] = reward[g];
                if (term[g] != 0) htmask |= (1u << i);
            } else { hr[i] = 0.0f; honemask |= (1u << i); }
        }
    }

    // ---------------- halo per-thread affine + warp suffix-compose ----------------
    float hA = 1.0f, hB;
    {
        float y = 0.0f;
        #pragma unroll
        for (int i = HITEMS - 1; i >= 0; --i) {
            float a = ((htmask >> i) & 1u) ? 0.0f : (((honemask >> i) & 1u) ? 1.0f : DISC);
            y = fmaf(a, y, hr[i]);
            hA *= a;
        }
        hB = y;
    }
    #pragma unroll
    for (int d = 1; d < 32; d <<= 1) {
        float a2 = __shfl_down_sync(FULLMASK, hA, d);
        float b2 = __shfl_down_sync(FULLMASK, hB, d);
        if (lane + d < 32) { hB = fmaf(hA, b2, hB); hA = hA * a2; }
    }

    // ---------------- owned pass 1: zero-carry values + chunk affine ----------------
    float A, B;
    if (ownFull) {
        #pragma unroll
        for (int q = 0; q < 4; ++q) {
            float y = 0.0f;
            #pragma unroll
            for (int i = 3; i >= 0; --i) {
                const int idx = 4 * q + i;
                float yp = ((tmask >> idx) & 1u) ? 0.0f : y;
                y = fmaf(DISC, yp, r[idx]);
                r[idx] = y;                      // value with zero carry at quarter end
            }
        }
        float A2 = ((tmask >> 8) & 0xFu) ? 0.0f : pw[4];
        float A1 = ((tmask >> 4) & 0xFu) ? 0.0f : pw[4];
        float V3 = r[12];
        float V2 = fmaf(A2, V3, r[8]);
        float V1 = fmaf(A1, V2, r[4]);
        #pragma unroll
        for (int q = 0; q < 3; ++q) {
            const float Cq = (q == 0) ? V1 : (q == 1) ? V2 : V3;
            #pragma unroll
            for (int i = 0; i < 4; ++i) {
                const int idx = 4 * q + i;
                unsigned bits = (tmask >> idx) & ((1u << (4 - i)) - 1u);
                float P = bits ? 0.0f : pw[4 - i];
                r[idx] = fmaf(P, Cq, r[idx]);    // now zero-CHUNK-carry value
            }
        }
        B = r[0];
        A = tmask ? 0.0f : pw[16];
    } else {
        float y = 0.0f; A = 1.0f;
        #pragma unroll
        for (int i = ITEMS - 1; i >= 0; --i) {
            float a = ((tmask >> i) & 1u) ? 0.0f : (((onemask >> i) & 1u) ? 1.0f : DISC);
            y = fmaf(a, y, r[i]);
            A *= a;
        }
        B = y;
    }

    // ---------------- warp suffix scan over per-thread (A,B) ----------------
    float Ai = A, Bi = B;
    #pragma unroll
    for (int d = 1; d < 32; d <<= 1) {
        float a2 = __shfl_down_sync(FULLMASK, Ai, d);
        float b2 = __shfl_down_sync(FULLMASK, Bi, d);
        if (lane + d < 32) { Bi = fmaf(Ai, b2, Bi); Ai = Ai * a2; }
    }
    float exA = __shfl_down_sync(FULLMASK, Ai, 1);
    float exB = __shfl_down_sync(FULLMASK, Bi, 1);
    if (lane == 31) { exA = 1.0f; exB = 0.0f; }

    if (lane == 0) {
        s_wA[wid] = Ai; s_wB[wid] = Bi;
        s_hA[wid] = hA; s_hB[wid] = hB;
    }
    __syncthreads();

    // ---------------- warp 0: cross-warp scans (owned exclusive + halo total) -----
    if (wid == 0) {
        bool v = lane < NWARPS;
        float wa = v ? s_wA[lane] : 1.0f;
        float wb = v ? s_wB[lane] : 0.0f;
        float ha = v ? s_hA[lane] : 1.0f;
        float hb = v ? s_hB[lane] : 0.0f;
        #pragma unroll
        for (int d = 1; d < 32; d <<= 1) {
            float a2 = __shfl_down_sync(FULLMASK, wa, d);
            float b2 = __shfl_down_sync(FULLMASK, wb, d);
            float a3 = __shfl_down_sync(FULLMASK, ha, d);
            float b3 = __shfl_down_sync(FULLMASK, hb, d);
            if (lane + d < 32) {
                wb = fmaf(wa, b2, wb); wa *= a2;
                hb = fmaf(ha, b3, hb); ha *= a3;
            }
        }
        float ecA = __shfl_down_sync(FULLMASK, wa, 1);
        float ecB = __shfl_down_sync(FULLMASK, wb, 1);
        if (v) {
            if (lane == NWARPS - 1) { ecA = 1.0f; ecB = 0.0f; }
            s_cA[lane] = ecA; s_cB[lane] = ecB;
        }
        if (lane == 0) s_yin = hb;     // halo composition applied to 0
    }
    __syncthreads();

    const float yin = s_yin;
    const float cA  = s_cA[wid];
    const float cB  = s_cB[wid];
    const float etA = exA * cA;
    const float etB = fmaf(exA, cB, exB);
    const float Yc  = fmaf(etA, yin, etB);    // carry entering this thread's chunk

    // ---------------- outputs ----------------
    if (ownFull) {
        #pragma unroll
        for (int i = 0; i < ITEMS; ++i) {
            float P = (tmask >> i) ? 0.0f : pw[ITEMS - i];
            r[i] = fmaf(P, Yc, r[i]);
        }
        float4* op = (float4*)(out + cs);
        __stcs(op + 0, make_float4(r[0],  r[1],  r[2],  r[3]));
        __stcs(op + 1, make_float4(r[4],  r[5],  r[6],  r[7]));
        __stcs(op + 2, make_float4(r[8],  r[9],  r[10], r[11]));
        __stcs(op + 3, make_float4(r[12], r[13], r[14], r[15]));
    } else {
        float y = Yc;
        #pragma unroll
        for (int i = ITEMS - 1; i >= 0; --i) {
            float a = ((tmask >> i) & 1u) ? 0.0f : (((onemask >> i) & 1u) ? 1.0f : DISC);
            y = fmaf(a, y, r[i]);
            int g = cs + i;
            if (g < n) out[g] = y;
        }
    }
}

extern "C" void kernel_launch(void* const* d_in, const int* in_sizes, int n_in,
                              void* d_out, int out_size)
{
    const int*   term   = (const int*)d_in[0];     // 'terminal' (bool -> int32)
    const float* reward = (const float*)d_in[1];   // 'reward' (f32)
    float*       out    = (float*)d_out;
    int n  = in_sizes[1];

    int npk = (n + 4095) / 4096;                   // pack_k: 512 els/warp, 8 warps/blk
    pack_k<<<npk, 256>>>(term, n);

    int nb = (n + TILE - 1) / TILE;                // 4096 for T=16777216
    scan_k<<<nb, THREADS>>>(reward, term, out, n);
}

// round 11
// speedup vs baseline: 1.1048x; 1.1048x over previous
#include <cuda_runtime.h>
#include <cstdint>

#define THREADS  256
#define ITEMS    16
#define TILE     (THREADS * ITEMS)    // 4096
#define HALO     1024
#define HITEMS   (HALO / THREADS)     // 4
#define NWARPS   (THREADS / 32)       // 8
#define FULLMASK 0xFFFFFFFFu
#define DISC     0.99f

// y[t] = a[t]*y[t+1] + r[t],  a = terminal[t] ? 0 : DISC,  y[n] = 0 (FINAL_REWARD=0).
// Halo truncation: carry through 1024 non-terminal steps scales by 0.99^1024=3.4e-5;
// RMS tile contribution ~2e-6 relative (threshold 1e-3). Blocks fully independent.
__global__ void __launch_bounds__(THREADS, 6)
scan_k(const float* __restrict__ reward,
       const int*  __restrict__ term,      // bool materialized as int32 (exactly 0/1)
       float*      __restrict__ out, int n)
{
    __shared__ float s_wA[NWARPS], s_wB[NWARPS];   // owned warp aggregates
    __shared__ float s_hA[NWARPS], s_hB[NWARPS];   // halo warp aggregates
    __shared__ float s_cA[NWARPS], s_cB[NWARPS];   // per-warp exclusive carries
    __shared__ float s_yin;

    // 0.99^k, k=0..16 (all uses have compile-time indices -> immediates)
    const float pw[17] = {
        1.0f, 0.99f, 0.9801f, 0.970299f, 0.96059601f,
        0.9509900499f, 0.941480149401f, 0.93206534790699f, 0.9227446944279201f,
        0.9135172474836409f, 0.9043820750088045f, 0.8953382542587165f,
        0.8863848717161293f, 0.8775210229989680f, 0.8687458127689783f,
        0.8600583546412885f, 0.8514577710948756f };

    const int t    = threadIdx.x;
    const int lane = t & 31;
    const int wid  = t >> 5;

    const int s  = (int)blockIdx.x * TILE;       // n <= ~2^27: int is safe
    const int cs = s + t * ITEMS;                // owned chunk start
    const int hs = s + TILE + t * HITEMS;        // halo chunk start

    const bool ownFull = (s + TILE        <= n);
    const bool extFull = (s + TILE + HALO <= n);

    // ---------------- loads (front-batched for MLP) ----------------
    float    r[ITEMS];
    unsigned tmask = 0u, onemask = 0u;
    float    hr[HITEMS];
    unsigned htmask = 0u, honemask = 0u;

    if (ownFull) {
        const float4* rp = (const float4*)(reward + cs);
        const int4*   tp = (const int4*)(term + cs);
        float4 v0 = __ldcg(rp + 0), v1 = __ldcg(rp + 1),
               v2 = __ldcg(rp + 2), v3 = __ldcg(rp + 3);
        int4   w0 = __ldcg(tp + 0), w1 = __ldcg(tp + 1),
               w2 = __ldcg(tp + 2), w3 = __ldcg(tp + 3);
        r[0]=v0.x; r[1]=v0.y; r[2]=v0.z; r[3]=v0.w;
        r[4]=v1.x; r[5]=v1.y; r[6]=v1.z; r[7]=v1.w;
        r[8]=v2.x; r[9]=v2.y; r[10]=v2.z; r[11]=v2.w;
        r[12]=v3.x; r[13]=v3.y; r[14]=v3.z; r[15]=v3.w;
        // terminal values are exactly 0/1 -> arithmetic nibble pack (3 IMAD each)
        unsigned n0 = (unsigned)(w0.x + 2*w0.y + 4*w0.z + 8*w0.w);
        unsigned n1 = (unsigned)(w1.x + 2*w1.y + 4*w1.z + 8*w1.w);
        unsigned n2 = (unsigned)(w2.x + 2*w2.y + 4*w2.z + 8*w2.w);
        unsigned n3 = (unsigned)(w3.x + 2*w3.y + 4*w3.z + 8*w3.w);
        tmask = n0 | (n1 << 4) | (n2 << 8) | (n3 << 12);
    } else {
        #pragma unroll
        for (int i = 0; i < ITEMS; ++i) {
            int g = cs + i;
            if (g < n) {
                r[i] = reward[g];
                if (term[g] != 0) tmask |= (1u << i);
            } else { r[i] = 0.0f; onemask |= (1u << i); }
        }
    }

    if (extFull) {
        float4 hv = __ldcg((const float4*)(reward + hs));
        int4   hw = __ldcg((const int4*)(term + hs));
        hr[0]=hv.x; hr[1]=hv.y; hr[2]=hv.z; hr[3]=hv.w;
        htmask = (unsigned)(hw.x + 2*hw.y + 4*hw.z + 8*hw.w);
    } else {
        #pragma unroll
        for (int i = 0; i < HITEMS; ++i) {
            int g = hs + i;
            if (g < n) {
                hr[i] = reward[g];
                if (term[g] != 0) htmask |= (1u << i);
            } else { hr[i] = 0.0f; honemask |= (1u << i); }
        }
    }

    // ---------------- halo per-thread affine + warp suffix-compose ----------------
    float hA = 1.0f, hB;
    {
        float y = 0.0f;
        #pragma unroll
        for (int i = HITEMS - 1; i >= 0; --i) {
            float a = ((htmask >> i) & 1u) ? 0.0f : (((honemask >> i) & 1u) ? 1.0f : DISC);
            y = fmaf(a, y, hr[i]);
            hA *= a;
        }
        hB = y;
    }
    #pragma unroll
    for (int d = 1; d < 32; d <<= 1) {
        float a2 = __shfl_down_sync(FULLMASK, hA, d);
        float b2 = __shfl_down_sync(FULLMASK, hB, d);
        if (lane + d < 32) { hB = fmaf(hA, b2, hB); hA = hA * a2; }
    }

    // ---------------- owned pass 1: zero-carry values + chunk affine ----------------
    float A, B;
    if (ownFull) {
        // 4 independent 4-item Horner chains (zero carry at each quarter end)
        #pragma unroll
        for (int q = 0; q < 4; ++q) {
            float y = 0.0f;
            #pragma unroll
            for (int i = 3; i >= 0; --i) {
                const int idx = 4 * q + i;
                float yp = ((tmask >> idx) & 1u) ? 0.0f : y;
                y = fmaf(DISC, yp, r[idx]);
                r[idx] = y;                      // value with zero carry at quarter end
            }
        }
        // quarter coefficients (closed form) + carry chain across quarters
        float A2 = ((tmask >> 8) & 0xFu) ? 0.0f : pw[4];
        float A1 = ((tmask >> 4) & 0xFu) ? 0.0f : pw[4];
        float V3 = r[12];
        float V2 = fmaf(A2, V3, r[8]);
        float V1 = fmaf(A1, V2, r[4]);
        // fix quarters 0..2 with their incoming carries (quarter 3 has carry 0)
        #pragma unroll
        for (int q = 0; q < 3; ++q) {
            const float Cq = (q == 0) ? V1 : (q == 1) ? V2 : V3;
            #pragma unroll
            for (int i = 0; i < 4; ++i) {
                const int idx = 4 * q + i;
                unsigned bits = (tmask >> idx) & ((1u << (4 - i)) - 1u);
                float P = bits ? 0.0f : pw[4 - i];
                r[idx] = fmaf(P, Cq, r[idx]);    // now zero-CHUNK-carry value
            }
        }
        B = r[0];
        A = tmask ? 0.0f : pw[16];
    } else {
        float y = 0.0f; A = 1.0f;
        #pragma unroll
        for (int i = ITEMS - 1; i >= 0; --i) {
            float a = ((tmask >> i) & 1u) ? 0.0f : (((onemask >> i) & 1u) ? 1.0f : DISC);
            y = fmaf(a, y, r[i]);
            A *= a;
        }
        B = y;
    }

    // ---------------- warp suffix scan over per-thread (A,B) ----------------
    float Ai = A, Bi = B;
    #pragma unroll
    for (int d = 1; d < 32; d <<= 1) {
        float a2 = __shfl_down_sync(FULLMASK, Ai, d);
        float b2 = __shfl_down_sync(FULLMASK, Bi, d);
        if (lane + d < 32) { Bi = fmaf(Ai, b2, Bi); Ai = Ai * a2; }
    }
    float exA = __shfl_down_sync(FULLMASK, Ai, 1);   // exclusive = inclusive of lane+1
    float exB = __shfl_down_sync(FULLMASK, Bi, 1);
    if (lane == 31) { exA = 1.0f; exB = 0.0f; }

    if (lane == 0) {
        s_wA[wid] = Ai; s_wB[wid] = Bi;
        s_hA[wid] = hA; s_hB[wid] = hB;
    }
    __syncthreads();

    // ---------------- warp 0: cross-warp scans (owned exclusive + halo total) -----
    if (wid == 0) {
        bool v = lane < NWARPS;
        float wa = v ? s_wA[lane] : 1.0f;
        float wb = v ? s_wB[lane] : 0.0f;
        float ha = v ? s_hA[lane] : 1.0f;
        float hb = v ? s_hB[lane] : 0.0f;
        #pragma unroll
        for (int d = 1; d < 32; d <<= 1) {
            float a2 = __shfl_down_sync(FULLMASK, wa, d);
            float b2 = __shfl_down_sync(FULLMASK, wb, d);
            float a3 = __shfl_down_sync(FULLMASK, ha, d);
            float b3 = __shfl_down_sync(FULLMASK, hb, d);
            if (lane + d < 32) {
                wb = fmaf(wa, b2, wb); wa *= a2;
                hb = fmaf(ha, b3, hb); ha *= a3;
            }
        }
        float ecA = __shfl_down_sync(FULLMASK, wa, 1);
        float ecB = __shfl_down_sync(FULLMASK, wb, 1);
        if (v) {
            if (lane == NWARPS - 1) { ecA = 1.0f; ecB = 0.0f; }
            s_cA[lane] = ecA; s_cB[lane] = ecB;
        }
        if (lane == 0) s_yin = hb;     // halo composition applied to 0
    }
    __syncthreads();

    const float yin = s_yin;
    const float cA  = s_cA[wid];
    const float cB  = s_cB[wid];
    const float etA = exA * cA;
    const float etB = fmaf(exA, cB, exB);
    const float Yc  = fmaf(etA, yin, etB);    // carry entering this thread's chunk

    // ---------------- outputs ----------------
    if (ownFull) {
        #pragma unroll
        for (int i = 0; i < ITEMS; ++i) {
            float P = (tmask >> i) ? 0.0f : pw[ITEMS - i];   // independent FFMAs
            r[i] = fmaf(P, Yc, r[i]);
        }
        float4* op = (float4*)(out + cs);
        __stcs(op + 0, make_float4(r[0],  r[1],  r[2],  r[3]));
        __stcs(op + 1, make_float4(r[4],  r[5],  r[6],  r[7]));
        __stcs(op + 2, make_float4(r[8],  r[9],  r[10], r[11]));
        __stcs(op + 3, make_float4(r[12], r[13], r[14], r[15]));
    } else {
        float y = Yc;
        #pragma unroll
        for (int i = ITEMS - 1; i >= 0; --i) {
            float a = ((tmask >> i) & 1u) ? 0.0f : (((onemask >> i) & 1u) ? 1.0f : DISC);
            y = fmaf(a, y, r[i]);
            int g = cs + i;
            if (g < n) out[g] = y;
        }
    }
}

extern "C" void kernel_launch(void* const* d_in, const int* in_sizes, int n_in,
                              void* d_out, int out_size)
{
    const int*   term   = (const int*)d_in[0];     // 'terminal' (bool -> int32, 0/1)
    const float* reward = (const float*)d_in[1];   // 'reward' (f32)
    float*       out    = (float*)d_out;
    int n  = in_sizes[1];
    int nb = (n + TILE - 1) / TILE;                // 4096 for T=16777216
    scan_k<<<nb, THREADS>>>(reward, term, out, n);
}

// round 12
// speedup vs baseline: 1.2189x; 1.1033x over previous
#include <cuda_runtime.h>
#include <cstdint>

#define THREADS  256
#define ITEMS    16
#define TILE     (THREADS * ITEMS)    // 4096
#define HALO     1024
#define NWARPS   (THREADS / 32)       // 8
#define FULLMASK 0xFFFFFFFFu
#define DISC     0.99f
#define PW4      0.96059601f          // 0.99^4

// y[t] = a[t]*y[t+1] + r[t],  a = terminal[t] ? 0 : DISC,  y[n] = 0.
// Halo truncation: 0.99^1024 = 3.4e-5 scale on the cut carry -> ~2e-6 RMS rel.
// Blocks fully independent; no flags, no atomics, no lookback.
//
// Layout: warp w owns 512 contiguous elements [s+512w, s+512w+512).
// Round r (0..3) covers its 128-element slice; lane l owns the 4-element segment
// at  s + 512w + 128r + 4l  -> every LDG.128/STG.128 is lane-contiguous (4 lines).
__global__ void __launch_bounds__(THREADS, 5)
scan_k(const float* __restrict__ reward,
       const int*  __restrict__ term,      // bool materialized as int32 (exactly 0/1)
       float*      __restrict__ out, int n)
{
    __shared__ float s_wA[NWARPS], s_wB[NWARPS];   // owned warp aggregates
    __shared__ float s_hA[NWARPS], s_hB[NWARPS];   // halo warp aggregates
    __shared__ float s_cA[NWARPS], s_cB[NWARPS];   // per-warp exclusive carries
    __shared__ float s_yin;

    const int t    = threadIdx.x;
    const int lane = t & 31;
    const int wid  = t >> 5;

    const int s     = (int)blockIdx.x * TILE;          // n < 2^31 elements
    const int fbase = (s >> 2) + wid * 128 + lane;     // float4 idx; round r: +32r
    const int e0    = s + wid * 512 + lane * 4;        // element idx of round-0 seg

    const bool ownFull = (s + TILE        <= n);
    const bool extFull = (s + TILE + HALO <= n);

    // ---------------- owned loads + per-segment affines ----------------
    float4   v[4];
    unsigned tm = 0u, om = 0u;       // terminal / padding nibbles, nibble r = round r
    float    segA[4], segB[4];

    if (ownFull) {
        const float4* rp = (const float4*)reward;
        const int4*   tp = (const int4*)term;
        #pragma unroll
        for (int r = 0; r < 4; ++r) {
            v[r] = rp[fbase + r * 32];
            int4 w = tp[fbase + r * 32];
            unsigned m = (unsigned)(w.x + 2*w.y + 4*w.z + 8*w.w);
            tm |= m << (4 * r);
            float y = v[r].w;                                  // a3*0 + r3
            y = fmaf((m & 4u) ? 0.0f : DISC, y, v[r].z);
            y = fmaf((m & 2u) ? 0.0f : DISC, y, v[r].y);
            y = fmaf((m & 1u) ? 0.0f : DISC, y, v[r].x);
            segB[r] = y;
            segA[r] = m ? 0.0f : PW4;
        }
    } else {
        #pragma unroll
        for (int r = 0; r < 4; ++r) {
            float rv[4];
            #pragma unroll
            for (int j = 0; j < 4; ++j) {
                int e = e0 + r * 128 + j;
                if (e < n) {
                    rv[j] = reward[e];
                    if (term[e] != 0) tm |= (1u << (4*r + j));
                } else { rv[j] = 0.0f; om |= (1u << (4*r + j)); }
            }
            v[r] = make_float4(rv[0], rv[1], rv[2], rv[3]);
            float y = 0.0f, A = 1.0f;
            #pragma unroll
            for (int j = 3; j >= 0; --j) {
                unsigned b = 4*r + j;
                float a = ((tm >> b) & 1u) ? 0.0f : (((om >> b) & 1u) ? 1.0f : DISC);
                y = fmaf(a, y, rv[j]);
                A *= a;
            }
            segB[r] = y; segA[r] = A;
        }
    }

    // ---------------- halo: one 4-element segment per thread (coalesced) ----------
    float hA = 1.0f, hB;
    {
        float hr[4]; unsigned hm = 0u, ho = 0u;
        const int hs = s + TILE + t * 4;
        if (extFull) {
            float4 hv = *(const float4*)(reward + hs);
            int4   hw = *(const int4*)(term + hs);
            hr[0]=hv.x; hr[1]=hv.y; hr[2]=hv.z; hr[3]=hv.w;
            hm = (unsigned)(hw.x + 2*hw.y + 4*hw.z + 8*hw.w);
        } else {
            #pragma unroll
            for (int i = 0; i < 4; ++i) {
                int g = hs + i;
                if (g < n) {
                    hr[i] = reward[g];
                    if (term[g] != 0) hm |= (1u << i);
                } else { hr[i] = 0.0f; ho |= (1u << i); }
            }
        }
        float y = 0.0f;
        #pragma unroll
        for (int i = 3; i >= 0; --i) {
            float a = ((hm >> i) & 1u) ? 0.0f : (((ho >> i) & 1u) ? 1.0f : DISC);
            y = fmaf(a, y, hr[i]);
            hA *= a;
        }
        hB = y;
    }
    #pragma unroll
    for (int d = 1; d < 32; d <<= 1) {
        float a2 = __shfl_down_sync(FULLMASK, hA, d);
        float b2 = __shfl_down_sync(FULLMASK, hB, d);
        if (lane + d < 32) { hB = fmaf(hA, b2, hB); hA = hA * a2; }
    }

    // ---------------- per-round warp suffix scans + warp aggregate ----------------
    float exA[4], exB[4], TA[4], TB[4];
    float WA = 1.0f, WB = 0.0f;
    #pragma unroll
    for (int r = 3; r >= 0; --r) {
        float Ai = segA[r], Bi = segB[r];
        #pragma unroll
        for (int d = 1; d < 32; d <<= 1) {
            float a2 = __shfl_down_sync(FULLMASK, Ai, d);
            float b2 = __shfl_down_sync(FULLMASK, Bi, d);
            if (lane + d < 32) { Bi = fmaf(Ai, b2, Bi); Ai = Ai * a2; }
        }
        float eA = __shfl_down_sync(FULLMASK, Ai, 1);   // exclusive = incl of lane+1
        float eB = __shfl_down_sync(FULLMASK, Bi, 1);
        if (lane == 31) { eA = 1.0f; eB = 0.0f; }
        exA[r] = eA; exB[r] = eB;
        TA[r] = __shfl_sync(FULLMASK, Ai, 0);           // round total
        TB[r] = __shfl_sync(FULLMASK, Bi, 0);
        if (r == 3) { WA = TA[3]; WB = TB[3]; }
        else        { WB = fmaf(TA[r], WB, TB[r]); WA = TA[r] * WA; }   // W = T_r ∘ W
    }

    if (lane == 0) {
        s_wA[wid] = WA; s_wB[wid] = WB;
        s_hA[wid] = hA; s_hB[wid] = hB;
    }
    __syncthreads();

    // ---------------- warp 0: cross-warp scans (owned exclusive + halo total) -----
    if (wid == 0) {
        bool v8 = lane < NWARPS;
        float wa = v8 ? s_wA[lane] : 1.0f;
        float wb = v8 ? s_wB[lane] : 0.0f;
        float ha = v8 ? s_hA[lane] : 1.0f;
        float hb = v8 ? s_hB[lane] : 0.0f;
        #pragma unroll
        for (int d = 1; d < 32; d <<= 1) {
            float a2 = __shfl_down_sync(FULLMASK, wa, d);
            float b2 = __shfl_down_sync(FULLMASK, wb, d);
            float a3 = __shfl_down_sync(FULLMASK, ha, d);
            float b3 = __shfl_down_sync(FULLMASK, hb, d);
            if (lane + d < 32) {
                wb = fmaf(wa, b2, wb); wa *= a2;
                hb = fmaf(ha, b3, hb); ha *= a3;
            }
        }
        float ecA = __shfl_down_sync(FULLMASK, wa, 1);
        float ecB = __shfl_down_sync(FULLMASK, wb, 1);
        if (v8) {
            if (lane == NWARPS - 1) { ecA = 1.0f; ecB = 0.0f; }
            s_cA[lane] = ecA; s_cB[lane] = ecB;
        }
        if (lane == 0) s_yin = hb;     // halo composition applied to 0
    }
    __syncthreads();

    // value entering this warp from the right
    const float yin = s_yin;
    float Y = fmaf(s_cA[wid], yin, s_cB[wid]);

    // ---------------- outputs: replay rounds right-to-left ----------------
    if (ownFull) {
        float4* op = (float4*)out;
        #pragma unroll
        for (int r = 3; r >= 0; --r) {
            float c = fmaf(exA[r], Y, exB[r]);     // carry entering this segment
            unsigned m = tm >> (4 * r);
            float y = c, o0, o1, o2, o3;
            y = fmaf((m & 8u) ? 0.0f : DISC, y, v[r].w); o3 = y;
            y = fmaf((m & 4u) ? 0.0f : DISC, y, v[r].z); o2 = y;
            y = fmaf((m & 2u) ? 0.0f : DISC, y, v[r].y); o1 = y;
            y = fmaf((m & 1u) ? 0.0f : DISC, y, v[r].x); o0 = y;
            __stcs(op + fbase + r * 32, make_float4(o0, o1, o2, o3));
            Y = fmaf(TA[r], Y, TB[r]);             // value entering round r-1
        }
    } else {
        #pragma unroll
        for (int r = 3; r >= 0; --r) {
            float y = fmaf(exA[r], Y, exB[r]);
            float rv[4] = { v[r].x, v[r].y, v[r].z, v[r].w };
            #pragma unroll
            for (int j = 3; j >= 0; --j) {
                unsigned b = 4*r + j;
                float a = ((tm >> b) & 1u) ? 0.0f : (((om >> b) & 1u) ? 1.0f : DISC);
                y = fmaf(a, y, rv[j]);
                int e = e0 + r * 128 + j;
                if (e < n) out[e] = y;
            }
            Y = fmaf(TA[r], Y, TB[r]);
        }
    }
}

extern "C" void kernel_launch(void* const* d_in, const int* in_sizes, int n_in,
                              void* d_out, int out_size)
{
    const int*   term   = (const int*)d_in[0];     // 'terminal' (bool -> int32, 0/1)
    const float* reward = (const float*)d_in[1];   // 'reward' (f32)
    float*       out    = (float*)d_out;
    int n  = in_sizes[1];
    int nb = (n + TILE - 1) / TILE;                // 4096 for T=16777216
    scan_k<<<nb, THREADS>>>(reward, term, out, n);
}

// round 13
// speedup vs baseline: 1.2454x; 1.0218x over previous
#include <cuda_runtime.h>
#include <cstdint>

#define THREADS  256
#define TILE     4096                 // per-tile elements (256 thr x 16)
#define KTILES   2                    // tiles per block, processed right-to-left
#define BSPAN    (TILE * KTILES)      // 8192
#define HALO     1024
#define NWARPS   (THREADS / 32)       // 8
#define FULLMASK 0xFFFFFFFFu
#define DISC     0.99f
#define PW4      0.96059601f          // 0.99^4

// y[t] = a[t]*y[t+1] + r[t],  a = terminal[t] ? 0 : DISC,  y[n] = 0.
// Halo truncation: 0.99^1024 = 3.4e-5 scale on the cut carry -> ~2e-6 RMS rel.
// Block processes KTILES consecutive tiles right-to-left; the tile-total affine
// gives the EXACT carry into the next (left) tile, so only one halo read/block.
//
// Layout inside a tile: warp w owns 512 contiguous elements; round r (0..3) is its
// 128-element slice; lane l owns 4 elements at  ts + 512w + 128r + 4l
// -> every LDG.128/STG.128 is lane-contiguous (4 cache lines per warp instruction).
__global__ void __launch_bounds__(THREADS, 5)
scan_k(const float* __restrict__ reward,
       const int*  __restrict__ term,      // bool materialized as int32 (exactly 0/1)
       float*      __restrict__ out, int n)
{
    __shared__ float s_wA[NWARPS], s_wB[NWARPS];   // owned warp aggregates
    __shared__ float s_cA[NWARPS], s_cB[NWARPS];   // per-warp exclusive carries
    __shared__ float s_hA[NWARPS], s_hB[NWARPS];   // halo warp aggregates
    __shared__ float s_tA, s_tB;                   // tile total affine
    __shared__ float s_yin;

    const int t    = threadIdx.x;
    const int lane = t & 31;
    const int wid  = t >> 5;

    const int bs = (int)blockIdx.x * BSPAN;        // block span start

    // ================= halo (once per block, right of the rightmost tile) =========
    {
        float hA = 1.0f, hB;
        float hr[4]; unsigned hm = 0u, ho = 0u;
        const int hs = bs + BSPAN + t * 4;
        if (hs + 4 <= n) {
            float4 hv = *(const float4*)(reward + hs);
            int4   hw = *(const int4*)(term + hs);
            hr[0]=hv.x; hr[1]=hv.y; hr[2]=hv.z; hr[3]=hv.w;
            hm = (unsigned)(hw.x + 2*hw.y + 4*hw.z + 8*hw.w);
        } else {
            #pragma unroll
            for (int i = 0; i < 4; ++i) {
                int g = hs + i;
                if (g < n) {
                    hr[i] = reward[g];
                    if (term[g] != 0) hm |= (1u << i);
                } else { hr[i] = 0.0f; ho |= (1u << i); }
            }
        }
        float y = 0.0f;
        #pragma unroll
        for (int i = 3; i >= 0; --i) {
            float a = ((hm >> i) & 1u) ? 0.0f : (((ho >> i) & 1u) ? 1.0f : DISC);
            y = fmaf(a, y, hr[i]);
            hA *= a;
        }
        hB = y;
        #pragma unroll
        for (int d = 1; d < 32; d <<= 1) {
            float a2 = __shfl_down_sync(FULLMASK, hA, d);
            float b2 = __shfl_down_sync(FULLMASK, hB, d);
            if (lane + d < 32) { hB = fmaf(hA, b2, hB); hA = hA * a2; }
        }
        if (lane == 0) { s_hA[wid] = hA; s_hB[wid] = hB; }
        __syncthreads();
        if (wid == 0) {
            bool v8 = lane < NWARPS;
            float ha = v8 ? s_hA[lane] : 1.0f;
            float hb = v8 ? s_hB[lane] : 0.0f;
            #pragma unroll
            for (int d = 1; d < 32; d <<= 1) {
                float a3 = __shfl_down_sync(FULLMASK, ha, d);
                float b3 = __shfl_down_sync(FULLMASK, hb, d);
                if (lane + d < 32) { hb = fmaf(ha, b3, hb); ha *= a3; }
            }
            if (lane == 0) s_yin = hb;          // halo composition applied to 0
        }
        __syncthreads();
    }
    float yin = s_yin;

    // ================= tiles, right-to-left ======================================
    #pragma unroll
    for (int ti = KTILES - 1; ti >= 0; --ti) {
        const int ts    = bs + ti * TILE;
        const int fbase = (ts >> 2) + wid * 128 + lane;   // float4 idx; round r: +32r
        const int e0    = ts + wid * 512 + lane * 4;
        const bool ownFull = (ts + TILE <= n);

        float4   v[4];
        unsigned tm = 0u, om = 0u;
        float    segA[4], segB[4];

        if (ownFull) {
            const float4* rp = (const float4*)reward;
            const int4*   tp = (const int4*)term;
            #pragma unroll
            for (int r = 0; r < 4; ++r) {
                v[r] = rp[fbase + r * 32];
                int4 w = tp[fbase + r * 32];
                unsigned m = (unsigned)(w.x + 2*w.y + 4*w.z + 8*w.w);
                tm |= m << (4 * r);
                float y = v[r].w;
                y = fmaf((m & 4u) ? 0.0f : DISC, y, v[r].z);
                y = fmaf((m & 2u) ? 0.0f : DISC, y, v[r].y);
                y = fmaf((m & 1u) ? 0.0f : DISC, y, v[r].x);
                segB[r] = y;
                segA[r] = m ? 0.0f : PW4;
            }
        } else {
            #pragma unroll
            for (int r = 0; r < 4; ++r) {
                float rv[4];
                #pragma unroll
                for (int j = 0; j < 4; ++j) {
                    int e = e0 + r * 128 + j;
                    if (e < n) {
                        rv[j] = reward[e];
                        if (term[e] != 0) tm |= (1u << (4*r + j));
                    } else { rv[j] = 0.0f; om |= (1u << (4*r + j)); }
                }
                v[r] = make_float4(rv[0], rv[1], rv[2], rv[3]);
                float y = 0.0f, A = 1.0f;
                #pragma unroll
                for (int j = 3; j >= 0; --j) {
                    unsigned b = 4*r + j;
                    float a = ((tm >> b) & 1u) ? 0.0f : (((om >> b) & 1u) ? 1.0f : DISC);
                    y = fmaf(a, y, rv[j]);
                    A *= a;
                }
                segB[r] = y; segA[r] = A;
            }
        }

        // per-round warp suffix scans + warp aggregate
        float exA[4], exB[4], TA[4], TB[4];
        float WA = 1.0f, WB = 0.0f;
        #pragma unroll
        for (int r = 3; r >= 0; --r) {
            float Ai = segA[r], Bi = segB[r];
            #pragma unroll
            for (int d = 1; d < 32; d <<= 1) {
                float a2 = __shfl_down_sync(FULLMASK, Ai, d);
                float b2 = __shfl_down_sync(FULLMASK, Bi, d);
                if (lane + d < 32) { Bi = fmaf(Ai, b2, Bi); Ai = Ai * a2; }
            }
            float eA = __shfl_down_sync(FULLMASK, Ai, 1);
            float eB = __shfl_down_sync(FULLMASK, Bi, 1);
            if (lane == 31) { eA = 1.0f; eB = 0.0f; }
            exA[r] = eA; exB[r] = eB;
            TA[r] = __shfl_sync(FULLMASK, Ai, 0);
            TB[r] = __shfl_sync(FULLMASK, Bi, 0);
            if (r == 3) { WA = TA[3]; WB = TB[3]; }
            else        { WB = fmaf(TA[r], WB, TB[r]); WA = TA[r] * WA; }
        }

        if (lane == 0) { s_wA[wid] = WA; s_wB[wid] = WB; }
        __syncthreads();

        if (wid == 0) {
            bool v8 = lane < NWARPS;
            float wa = v8 ? s_wA[lane] : 1.0f;
            float wb = v8 ? s_wB[lane] : 0.0f;
            #pragma unroll
            for (int d = 1; d < 32; d <<= 1) {
                float a2 = __shfl_down_sync(FULLMASK, wa, d);
                float b2 = __shfl_down_sync(FULLMASK, wb, d);
                if (lane + d < 32) { wb = fmaf(wa, b2, wb); wa *= a2; }
            }
            float ecA = __shfl_down_sync(FULLMASK, wa, 1);
            float ecB = __shfl_down_sync(FULLMASK, wb, 1);
            if (v8) {
                if (lane == NWARPS - 1) { ecA = 1.0f; ecB = 0.0f; }
                s_cA[lane] = ecA; s_cB[lane] = ecB;
            }
            if (lane == 0) { s_tA = wa; s_tB = wb; }   // tile total (lane 0 inclusive)
        }
        __syncthreads();

        float Y = fmaf(s_cA[wid], yin, s_cB[wid]);     // value entering this warp

        if (ownFull) {
            float4* op = (float4*)out;
            #pragma unroll
            for (int r = 3; r >= 0; --r) {
                float c = fmaf(exA[r], Y, exB[r]);     // carry entering this segment
                unsigned m = tm >> (4 * r);
                float y = c, o0, o1, o2, o3;
                y = fmaf((m & 8u) ? 0.0f : DISC, y, v[r].w); o3 = y;
                y = fmaf((m & 4u) ? 0.0f : DISC, y, v[r].z); o2 = y;
                y = fmaf((m & 2u) ? 0.0f : DISC, y, v[r].y); o1 = y;
                y = fmaf((m & 1u) ? 0.0f : DISC, y, v[r].x); o0 = y;
                __stcs(op + fbase + r * 32, make_float4(o0, o1, o2, o3));
                Y = fmaf(TA[r], Y, TB[r]);             // value entering round r-1
            }
        } else {
            #pragma unroll
            for (int r = 3; r >= 0; --r) {
                float y = fmaf(exA[r], Y, exB[r]);
                float rv[4] = { v[r].x, v[r].y, v[r].z, v[r].w };
                #pragma unroll
                for (int j = 3; j >= 0; --j) {
                    unsigned b = 4*r + j;
                    float a = ((tm >> b) & 1u) ? 0.0f : (((om >> b) & 1u) ? 1.0f : DISC);
                    y = fmaf(a, y, rv[j]);
                    int e = e0 + r * 128 + j;
                    if (e < n) out[e] = y;
                }
                Y = fmaf(TA[r], Y, TB[r]);
            }
        }

        // exact carry into the next (left) tile
        yin = fmaf(s_tA, yin, s_tB);
    }
}

extern "C" void kernel_launch(void* const* d_in, const int* in_sizes, int n_in,
                              void* d_out, int out_size)
{
    const int*   term   = (const int*)d_in[0];     // 'terminal' (bool -> int32, 0/1)
    const float* reward = (const float*)d_in[1];   // 'reward' (f32)
    float*       out    = (float*)d_out;
    int n  = in_sizes[1];
    int nb = (n + BSPAN - 1) / BSPAN;              // 2048 for T=16777216
    scan_k<<<nb, THREADS>>>(reward, term, out, n);
}